// round 4
// baseline (speedup 1.0000x reference)
#include <cuda_runtime.h>

#define BB 8
#define NN 2048
#define DD 256
#define M_TOT (BB * NN)          // 16384
#define NEG_INF_F (-1000000000.0f)
#define SLOPE 0.2f

// Scratch (device globals: no allocation allowed in kernel_launch)
__device__ float g_h[M_TOT * DD];    // 16 MB
__device__ float g_hl[M_TOT];
__device__ float g_hr[M_TOT];
__device__ float g_m[M_TOT];
__device__ float g_rz[M_TOT];

// ---------------------------------------------------------------------------
// K1: h[m][o] = sum_d x[m][d] * W[o][d]   (M=16384, K=256, N=256)
// 64x64 block tile, TK=32, 256 threads, 4x4 micro-tile, FFMA2 inner loop.
// ---------------------------------------------------------------------------
__global__ __launch_bounds__(256) void k1_gemm_h(const float* __restrict__ x,
                                                 const float* __restrict__ W) {
    __shared__ float Xs[32][68];   // [k][i], padded (68*4B = 272B, 16B aligned)
    __shared__ float Ws[32][68];   // [k][o]

    const int i0 = blockIdx.x * 64;
    const int o0 = blockIdx.y * 64;
    const int t  = threadIdx.x;
    const int ty = t >> 4;         // 0..15 -> i group
    const int tx = t & 15;         // 0..15 -> o group

    const int lrow = t >> 3;       // 0..31
    const int lcol = (t & 7) * 4;  // 0,4,..,28

    // acc2[ii][p] packs out columns (tx*4 + 2p, tx*4 + 2p + 1)
    unsigned long long acc2[4][2];
#pragma unroll
    for (int a = 0; a < 4; a++) {
        acc2[a][0] = 0ULL;
        acc2[a][1] = 0ULL;
    }

    for (int k0 = 0; k0 < 256; k0 += 32) {
#pragma unroll
        for (int rr = 0; rr < 64; rr += 32) {
            float4 xv = *(const float4*)&x[(i0 + lrow + rr) * 256 + k0 + lcol];
            Xs[lcol + 0][lrow + rr] = xv.x;
            Xs[lcol + 1][lrow + rr] = xv.y;
            Xs[lcol + 2][lrow + rr] = xv.z;
            Xs[lcol + 3][lrow + rr] = xv.w;
            float4 wv = *(const float4*)&W[(o0 + lrow + rr) * 256 + k0 + lcol];
            Ws[lcol + 0][lrow + rr] = wv.x;
            Ws[lcol + 1][lrow + rr] = wv.y;
            Ws[lcol + 2][lrow + rr] = wv.z;
            Ws[lcol + 3][lrow + rr] = wv.w;
        }
        __syncthreads();
#pragma unroll 8
        for (int k = 0; k < 32; k++) {
            float av[4];
            *(float4*)av = *(const float4*)&Xs[k][ty * 4];
            // b pairs: 4 contiguous floats = 2 packed fp32x2
            ulonglong2 bp = *(const ulonglong2*)&Ws[k][tx * 4];
            unsigned long long b2[2] = {bp.x, bp.y};
#pragma unroll
            for (int ii = 0; ii < 4; ii++) {
                unsigned long long a2;
                unsigned int abits = __float_as_uint(av[ii]);
                asm("mov.b64 %0, {%1, %1};" : "=l"(a2) : "r"(abits));
#pragma unroll
                for (int p = 0; p < 2; p++)
                    asm("fma.rn.f32x2 %0, %1, %2, %0;"
                        : "+l"(acc2[ii][p])
                        : "l"(a2), "l"(b2[p]));
            }
        }
        __syncthreads();
    }

#pragma unroll
    for (int ii = 0; ii < 4; ii++) {
        int row = i0 + ty * 4 + ii;
        float2 r0 = *(float2*)&acc2[ii][0];
        float2 r1 = *(float2*)&acc2[ii][1];
        *(float4*)&g_h[row * 256 + o0 + tx * 4] =
            make_float4(r0.x, r0.y, r1.x, r1.y);
    }
}

// ---------------------------------------------------------------------------
// K1b: hl[m] = h[m,:] . a[0:256],  hr[m] = h[m,:] . a[256:512]
// One warp per row.
// ---------------------------------------------------------------------------
__global__ __launch_bounds__(256) void k1b_proj(const float* __restrict__ a) {
    int row  = blockIdx.x * 8 + (threadIdx.x >> 5);
    int lane = threadIdx.x & 31;
    const float* hrow = &g_h[row * 256];
    float sl = 0.0f, sr = 0.0f;
#pragma unroll
    for (int q = 0; q < 8; q++) {
        int o = lane + q * 32;
        float hv = hrow[o];
        sl += hv * a[o];
        sr += hv * a[256 + o];
    }
#pragma unroll
    for (int s = 16; s > 0; s >>= 1) {
        sl += __shfl_xor_sync(0xFFFFFFFFu, sl, s);
        sr += __shfl_xor_sync(0xFFFFFFFFu, sr, s);
    }
    if (lane == 0) { g_hl[row] = sl; g_hr[row] = sr; }
}

// ---------------------------------------------------------------------------
// K2: per row (b,i): m = max_j e_ij, rz = 1/sum_j exp(e_ij - m)
// e_ij = adj ? leaky(hl_i + hr_j) : NEG_INF. One block per row.
// ---------------------------------------------------------------------------
__global__ __launch_bounds__(256) void k2_stats(const int* __restrict__ adj) {
    __shared__ float es[2048];
    __shared__ float red[256];
    const int row = blockIdx.x;        // b*2048 + i
    const int b   = row >> 11;
    const int t   = threadIdx.x;

    const float hli = g_hl[row];
    const int*   arow = &adj[row * 2048];
    const float* hrb  = &g_hr[b * 2048];

    float mx = -3.4e38f;
    for (int j = t; j < 2048; j += 256) {
        int   av = arow[j];
        float s  = hli + hrb[j];
        float e  = s > 0.0f ? s : SLOPE * s;
        e        = av ? e : NEG_INF_F;
        es[j]    = e;
        mx       = fmaxf(mx, e);
    }
    red[t] = mx;
    __syncthreads();
#pragma unroll
    for (int s = 128; s > 0; s >>= 1) {
        if (t < s) red[t] = fmaxf(red[t], red[t + s]);
        __syncthreads();
    }
    float m = red[0];
    __syncthreads();

    float sum = 0.0f;
    for (int j = t; j < 2048; j += 256) sum += __expf(es[j] - m);
    red[t] = sum;
    __syncthreads();
#pragma unroll
    for (int s = 128; s > 0; s >>= 1) {
        if (t < s) red[t] += red[t + s];
        __syncthreads();
    }
    if (t == 0) {
        g_m[row]  = m;
        g_rz[row] = 1.0f / red[0];
    }
}

// ---------------------------------------------------------------------------
// K3: out[b,i,:] = sum_j w_ij * h[b,j,:]
//     w_ij = adj ? exp(leaky(hl_i + hr_j) - m_i) * rz_i : 0
// Tile: TI=64, TO=128, TJ=32; 256 threads; 4i x 8o micro-tile per thread.
// Inner loop uses packed fma.rn.f32x2 (FFMA2): 2 fp32 FMA per issue slot.
// ---------------------------------------------------------------------------
__global__ __launch_bounds__(256) void k3_aggregate(const int* __restrict__ adj,
                                                    float* __restrict__ out) {
    __shared__ float Hs[32][132];       // [j][o], 128 used, padded
    __shared__ float ws[64][33];        // [i][j], padded (conflict-free STS)
    __shared__ float s_hl[64], s_m[64], s_rz[64];

    const int b  = blockIdx.y;
    const int i0 = blockIdx.x * 64;
    const int o0 = blockIdx.z * 128;
    const int t  = threadIdx.x;
    const int row0 = b * 2048 + i0;

    if (t < 64) {
        s_hl[t] = g_hl[row0 + t];
        s_m[t]  = g_m[row0 + t];
        s_rz[t] = g_rz[row0 + t];
    }
    __syncthreads();

    const int ty = t >> 4;          // 0..15 -> i group (4 rows)
    const int tx = t & 15;          // 0..15 -> o group (8 cols)
    const int wj  = t & 31;         // j lane for w generation
    const int wib = t >> 5;         // 0..7  i base for w generation
    const int hj = t >> 3;          // 0..31 Hs row
    const int hc = (t & 7) * 4;     // Hs col base

    const float* hrb = &g_hr[b * 2048];

    // acc2[ii][p] packs out columns (tx*8 + 2p, tx*8 + 2p + 1) as fp32x2
    unsigned long long acc2[4][4];
#pragma unroll
    for (int a = 0; a < 4; a++)
#pragma unroll
        for (int c = 0; c < 4; c++) acc2[a][c] = 0ULL;

    for (int j0 = 0; j0 < 2048; j0 += 32) {
        // Load h tile [32 x 128]
        const float* hsrc = &g_h[(b * 2048 + j0 + hj) * 256 + o0];
#pragma unroll
        for (int q = 0; q < 4; q++) {
            *(float4*)&Hs[hj][hc + q * 32] = *(const float4*)&hsrc[hc + q * 32];
        }
        // Generate w tile [64 x 32]
        {
            float hrj = hrb[j0 + wj];
            const int* arow = &adj[(b * 2048 + i0 + wib) * 2048 + j0 + wj];
#pragma unroll
            for (int r = 0; r < 8; r++) {
                int ii = wib + r * 8;
                int av = arow[r * 8 * 2048];
                float s = s_hl[ii] + hrj;
                float e = s > 0.0f ? s : SLOPE * s;
                float w = av ? __expf(e - s_m[ii]) * s_rz[ii] : 0.0f;
                ws[ii][wj] = w;
            }
        }
        __syncthreads();

#pragma unroll 8
        for (int j = 0; j < 32; j++) {
            // Broadcast-pack w_i into both fp32x2 lanes
            unsigned long long w2[4];
#pragma unroll
            for (int ii = 0; ii < 4; ii++) {
                unsigned int wbits = __float_as_uint(ws[ty * 4 + ii][j]);
                asm("mov.b64 %0, {%1, %1};" : "=l"(w2[ii]) : "r"(wbits));
            }
            // h pairs: 8 contiguous floats = 4 packed fp32x2
            ulonglong2 hA = *(const ulonglong2*)&Hs[j][tx * 8];
            ulonglong2 hB = *(const ulonglong2*)&Hs[j][tx * 8 + 4];
            unsigned long long h2[4] = {hA.x, hA.y, hB.x, hB.y};
#pragma unroll
            for (int ii = 0; ii < 4; ii++)
#pragma unroll
                for (int p = 0; p < 4; p++)
                    asm("fma.rn.f32x2 %0, %1, %2, %0;"
                        : "+l"(acc2[ii][p])
                        : "l"(w2[ii]), "l"(h2[p]));
        }
        __syncthreads();
    }

#pragma unroll
    for (int ii = 0; ii < 4; ii++) {
        int i = i0 + ty * 4 + ii;
        float* orow = &out[(b * 2048 + i) * 256 + o0 + tx * 8];
        float2 r0 = *(float2*)&acc2[ii][0];
        float2 r1 = *(float2*)&acc2[ii][1];
        float2 r2 = *(float2*)&acc2[ii][2];
        float2 r3 = *(float2*)&acc2[ii][3];
        *(float4*)&orow[0] = make_float4(r0.x, r0.y, r1.x, r1.y);
        *(float4*)&orow[4] = make_float4(r2.x, r2.y, r3.x, r3.y);
    }
}

// ---------------------------------------------------------------------------
extern "C" void kernel_launch(void* const* d_in, const int* in_sizes, int n_in,
                              void* d_out, int out_size) {
    const float* x   = (const float*)d_in[0];   // [8, 2048, 256]
    const int*   adj = (const int*)  d_in[1];   // [8, 2048, 2048]
    const float* W   = (const float*)d_in[2];   // [256, 256]
    const float* a   = (const float*)d_in[3];   // [1, 512]
    float* out = (float*)d_out;                 // [8, 2048, 256]

    k1_gemm_h<<<dim3(M_TOT / 64, DD / 64), 256>>>(x, W);
    k1b_proj<<<M_TOT / 8, 256>>>(a);
    k2_stats<<<M_TOT, 256>>>(adj);
    k3_aggregate<<<dim3(NN / 64, BB, DD / 128), 256>>>(adj, out);
}

// round 7
// speedup vs baseline: 1.6250x; 1.6250x over previous
#include <cuda_runtime.h>

#define BB 8
#define NN 2048
#define DD 256
#define M_TOT (BB * NN)          // 16384
#define NEG_INF_F (-1000000000.0f)
#define SLOPE 0.2f

// Scratch (device globals: no allocation allowed in kernel_launch)
__device__ float g_h[M_TOT * DD];    // 16 MB
__device__ float g_hl[M_TOT];
__device__ float g_hr[M_TOT];
__device__ float g_m[M_TOT];
__device__ float g_rz[M_TOT];

// ---------------------------------------------------------------------------
// K1: h[m][o] = sum_d x[m][d] * W[o][d]   (M=16384, K=256, N=256)
// 128x128 block tile, TK=32, 256 threads, 8i x 8o micro-tile, FFMA2.
// Thread owns cols tx*4..+3 and 64+tx*4..+3 (2-way-min LDS.128 conflicts).
// ---------------------------------------------------------------------------
__global__ __launch_bounds__(256, 2) void k1_gemm_h(const float* __restrict__ x,
                                                    const float* __restrict__ W) {
    __shared__ float Xs[32][132];   // [k][i]
    __shared__ float Ws[32][132];   // [k][o]

    const int i0 = blockIdx.x * 128;
    const int o0 = blockIdx.y * 128;
    const int t  = threadIdx.x;
    const int ty = t >> 4;          // 0..15 -> i group of 8
    const int tx = t & 15;          // 0..15 -> o group (4 + 4 split)

    const int lrow = t >> 3;        // 0..31
    const int lcol = (t & 7) * 4;   // 0,4,..,28

    unsigned long long acc2[8][4];
#pragma unroll
    for (int a = 0; a < 8; a++)
#pragma unroll
        for (int c = 0; c < 4; c++) acc2[a][c] = 0ULL;

    for (int k0 = 0; k0 < 256; k0 += 32) {
#pragma unroll
        for (int rr = 0; rr < 128; rr += 32) {
            float4 xv = *(const float4*)&x[(i0 + lrow + rr) * 256 + k0 + lcol];
            Xs[lcol + 0][lrow + rr] = xv.x;
            Xs[lcol + 1][lrow + rr] = xv.y;
            Xs[lcol + 2][lrow + rr] = xv.z;
            Xs[lcol + 3][lrow + rr] = xv.w;
            float4 wv = *(const float4*)&W[(o0 + lrow + rr) * 256 + k0 + lcol];
            Ws[lcol + 0][lrow + rr] = wv.x;
            Ws[lcol + 1][lrow + rr] = wv.y;
            Ws[lcol + 2][lrow + rr] = wv.z;
            Ws[lcol + 3][lrow + rr] = wv.w;
        }
        __syncthreads();
#pragma unroll 8
        for (int k = 0; k < 32; k++) {
            // b pairs: cols tx*4..+3 and 64+tx*4..+3 -> 4 packed fp32x2
            ulonglong2 bA = *(const ulonglong2*)&Ws[k][tx * 4];
            ulonglong2 bB = *(const ulonglong2*)&Ws[k][64 + tx * 4];
            unsigned long long b2[4] = {bA.x, bA.y, bB.x, bB.y};
#pragma unroll
            for (int ii = 0; ii < 8; ii++) {
                unsigned long long a2;
                unsigned int abits = __float_as_uint(Xs[k][ty * 8 + ii]);
                asm("mov.b64 %0, {%1, %1};" : "=l"(a2) : "r"(abits));
#pragma unroll
                for (int p = 0; p < 4; p++)
                    asm("fma.rn.f32x2 %0, %1, %2, %0;"
                        : "+l"(acc2[ii][p])
                        : "l"(a2), "l"(b2[p]));
            }
        }
        __syncthreads();
    }

#pragma unroll
    for (int ii = 0; ii < 8; ii++) {
        int row = i0 + ty * 8 + ii;
        float2 r0 = *(float2*)&acc2[ii][0];
        float2 r1 = *(float2*)&acc2[ii][1];
        float2 r2 = *(float2*)&acc2[ii][2];
        float2 r3 = *(float2*)&acc2[ii][3];
        *(float4*)&g_h[row * 256 + o0 + tx * 4]      = make_float4(r0.x, r0.y, r1.x, r1.y);
        *(float4*)&g_h[row * 256 + o0 + 64 + tx * 4] = make_float4(r2.x, r2.y, r3.x, r3.y);
    }
}

// ---------------------------------------------------------------------------
// K1b: hl[m] = h[m,:] . a[0:256],  hr[m] = h[m,:] . a[256:512]
// One warp per row.
// ---------------------------------------------------------------------------
__global__ __launch_bounds__(256) void k1b_proj(const float* __restrict__ a) {
    int row  = blockIdx.x * 8 + (threadIdx.x >> 5);
    int lane = threadIdx.x & 31;
    const float* hrow = &g_h[row * 256];
    float sl = 0.0f, sr = 0.0f;
#pragma unroll
    for (int q = 0; q < 8; q++) {
        int o = lane + q * 32;
        float hv = hrow[o];
        sl += hv * a[o];
        sr += hv * a[256 + o];
    }
#pragma unroll
    for (int s = 16; s > 0; s >>= 1) {
        sl += __shfl_xor_sync(0xFFFFFFFFu, sl, s);
        sr += __shfl_xor_sync(0xFFFFFFFFu, sr, s);
    }
    if (lane == 0) { g_hl[row] = sl; g_hr[row] = sr; }
}

// ---------------------------------------------------------------------------
// K2: per row (b,i): m = max_j e_ij, rz = 1/sum_j exp(e_ij - m)
// e_ij = adj ? leaky(hl_i + hr_j) : NEG_INF. One block (256t) per row.
// Vectorized int4/float4 loads; warp-shuffle reductions (2 syncthreads).
// ---------------------------------------------------------------------------
__global__ __launch_bounds__(256) void k2_stats(const int* __restrict__ adj) {
    __shared__ float es[2048];
    __shared__ float red_m[8];
    __shared__ float red_s[8];
    const int row  = blockIdx.x;        // b*2048 + i
    const int b    = row >> 11;
    const int t    = threadIdx.x;
    const int lane = t & 31;
    const int wid  = t >> 5;

    const float hli = g_hl[row];
    const int*   arow = &adj[row * 2048];
    const float* hrb  = &g_hr[b * 2048];

    float mx = -3.4e38f;
#pragma unroll
    for (int q = 0; q < 2; q++) {
        int j4 = (t + q * 256) * 4;            // 4-aligned j base
        int4   av = *(const int4*)&arow[j4];
        float4 hv = *(const float4*)&hrb[j4];
        float e0, e1, e2, e3;
        {
            float s = hli + hv.x; float e = s > 0.0f ? s : SLOPE * s;
            e0 = av.x ? e : NEG_INF_F;
        }
        {
            float s = hli + hv.y; float e = s > 0.0f ? s : SLOPE * s;
            e1 = av.y ? e : NEG_INF_F;
        }
        {
            float s = hli + hv.z; float e = s > 0.0f ? s : SLOPE * s;
            e2 = av.z ? e : NEG_INF_F;
        }
        {
            float s = hli + hv.w; float e = s > 0.0f ? s : SLOPE * s;
            e3 = av.w ? e : NEG_INF_F;
        }
        *(float4*)&es[j4] = make_float4(e0, e1, e2, e3);
        mx = fmaxf(mx, fmaxf(fmaxf(e0, e1), fmaxf(e2, e3)));
    }
    // warp max -> block max via 8-entry shared
#pragma unroll
    for (int s = 16; s > 0; s >>= 1)
        mx = fmaxf(mx, __shfl_xor_sync(0xFFFFFFFFu, mx, s));
    if (lane == 0) red_m[wid] = mx;
    __syncthreads();
    float m = fmaxf(fmaxf(fmaxf(red_m[0], red_m[1]), fmaxf(red_m[2], red_m[3])),
                    fmaxf(fmaxf(red_m[4], red_m[5]), fmaxf(red_m[6], red_m[7])));

    float sum = 0.0f;
#pragma unroll
    for (int q = 0; q < 2; q++) {
        int j4 = (t + q * 256) * 4;
        float4 ev = *(const float4*)&es[j4];
        sum += __expf(ev.x - m) + __expf(ev.y - m)
             + __expf(ev.z - m) + __expf(ev.w - m);
    }
#pragma unroll
    for (int s = 16; s > 0; s >>= 1)
        sum += __shfl_xor_sync(0xFFFFFFFFu, sum, s);
    if (lane == 0) red_s[wid] = sum;
    __syncthreads();
    if (t == 0) {
        float tot = (red_s[0] + red_s[1]) + (red_s[2] + red_s[3])
                  + (red_s[4] + red_s[5]) + (red_s[6] + red_s[7]);
        g_m[row]  = m;
        g_rz[row] = 1.0f / tot;
    }
}

// ---------------------------------------------------------------------------
// K3: out[b,i,:] = sum_j w_ij * h[b,j,:]
//     w_ij = adj ? exp(leaky(hl_i + hr_j) - m_i) * rz_i : 0
// Tile: TI=128, TO=128, TJ=32; 256 threads; 8i x 8o micro-tile, FFMA2.
// Thread owns cols tx*4..+3 and 64+tx*4..+3.
// ---------------------------------------------------------------------------
__global__ __launch_bounds__(256, 2) void k3_aggregate(const int* __restrict__ adj,
                                                       float* __restrict__ out) {
    __shared__ float Hs[32][132];        // [j][o], 128 used, padded
    __shared__ float ws[128][33];        // [i][j], padded
    __shared__ float s_hl[128], s_m[128], s_rz[128];

    const int b  = blockIdx.y;
    const int i0 = blockIdx.x * 128;
    const int o0 = blockIdx.z * 128;
    const int t  = threadIdx.x;
    const int row0 = b * 2048 + i0;

    if (t < 128) {
        s_hl[t] = g_hl[row0 + t];
        s_m[t]  = g_m[row0 + t];
        s_rz[t] = g_rz[row0 + t];
    }
    __syncthreads();

    const int ty = t >> 4;          // 0..15 -> i group of 8
    const int tx = t & 15;          // 0..15 -> o group (4 + 4 split)
    const int wj  = t & 31;         // j lane for w generation
    const int wib = t >> 5;         // 0..7  i base for w generation
    const int hj = t >> 3;          // 0..31 Hs row
    const int hc = (t & 7) * 4;     // Hs col base

    const float* hrb = &g_hr[b * 2048];

    unsigned long long acc2[8][4];
#pragma unroll
    for (int a = 0; a < 8; a++)
#pragma unroll
        for (int c = 0; c < 4; c++) acc2[a][c] = 0ULL;

    for (int j0 = 0; j0 < 2048; j0 += 32) {
        // Load h tile [32 x 128]
        const float* hsrc = &g_h[(b * 2048 + j0 + hj) * 256 + o0];
#pragma unroll
        for (int q = 0; q < 4; q++) {
            *(float4*)&Hs[hj][hc + q * 32] = *(const float4*)&hsrc[hc + q * 32];
        }
        // Generate w tile [128 x 32]
        {
            float hrj = hrb[j0 + wj];
            const int* arow = &adj[(b * 2048 + i0 + wib) * 2048 + j0 + wj];
#pragma unroll
            for (int r = 0; r < 16; r++) {
                int ii = wib + r * 8;
                int av = arow[r * 8 * 2048];
                float s = s_hl[ii] + hrj;
                float e = s > 0.0f ? s : SLOPE * s;
                float w = av ? __expf(e - s_m[ii]) * s_rz[ii] : 0.0f;
                ws[ii][wj] = w;
            }
        }
        __syncthreads();

#pragma unroll 8
        for (int j = 0; j < 32; j++) {
            // h pairs: cols tx*4..+3 and 64+tx*4..+3 -> 4 packed fp32x2
            ulonglong2 hA = *(const ulonglong2*)&Hs[j][tx * 4];
            ulonglong2 hB = *(const ulonglong2*)&Hs[j][64 + tx * 4];
            unsigned long long h2[4] = {hA.x, hA.y, hB.x, hB.y};
#pragma unroll
            for (int ii = 0; ii < 8; ii++) {
                unsigned long long w2;
                unsigned int wbits = __float_as_uint(ws[ty * 8 + ii][j]);
                asm("mov.b64 %0, {%1, %1};" : "=l"(w2) : "r"(wbits));
#pragma unroll
                for (int p = 0; p < 4; p++)
                    asm("fma.rn.f32x2 %0, %1, %2, %0;"
                        : "+l"(acc2[ii][p])
                        : "l"(w2), "l"(h2[p]));
            }
        }
        __syncthreads();
    }

#pragma unroll
    for (int ii = 0; ii < 8; ii++) {
        int i = i0 + ty * 8 + ii;
        float* orow = &out[(b * 2048 + i) * 256 + o0];
        float2 r0 = *(float2*)&acc2[ii][0];
        float2 r1 = *(float2*)&acc2[ii][1];
        float2 r2 = *(float2*)&acc2[ii][2];
        float2 r3 = *(float2*)&acc2[ii][3];
        *(float4*)&orow[tx * 4]      = make_float4(r0.x, r0.y, r1.x, r1.y);
        *(float4*)&orow[64 + tx * 4] = make_float4(r2.x, r2.y, r3.x, r3.y);
    }
}

// ---------------------------------------------------------------------------
extern "C" void kernel_launch(void* const* d_in, const int* in_sizes, int n_in,
                              void* d_out, int out_size) {
    const float* x   = (const float*)d_in[0];   // [8, 2048, 256]
    const int*   adj = (const int*)  d_in[1];   // [8, 2048, 2048]
    const float* W   = (const float*)d_in[2];   // [256, 256]
    const float* a   = (const float*)d_in[3];   // [1, 512]
    float* out = (float*)d_out;                 // [8, 2048, 256]

    k1_gemm_h<<<dim3(M_TOT / 128, DD / 128), 256>>>(x, W);
    k1b_proj<<<M_TOT / 8, 256>>>(a);
    k2_stats<<<M_TOT, 256>>>(adj);
    k3_aggregate<<<dim3(NN / 128, BB, DD / 128), 256>>>(adj, out);
}